// round 12
// baseline (speedup 1.0000x reference)
#include <cuda_runtime.h>
#include <cuda_fp16.h>

// DeformationGrid: trilinear interpolation of a (160,160,160,3) f32 grid at
// 4,194,304 random points.
//
// R10: trilerp sits at the L1tex WITHIN-LDG replay floor (2.07 cyc/wf, each
// divergent LDG.E.128 carries ~18 wavefronts). Split each gather into FOUR
// predicated sub-LDGs (one per 8-lane group, ~4.5 lines each) so wavefronts
// become cross-LDG (~1.0 cyc/wf) instead of within-LDG replays. Pointers are
// laundered so ptxas can't re-merge the four loads. Same math, same layout.

static constexpr int NX = 160, NY = 160, NZ = 160;
static constexpr int NVOX = NX * NY * NZ;

// 16B fp16 z-pair entry, y-fastest: g_grid[(x*NZ + z)*NY + y]. 65.5 MB.
__device__ uint4 g_grid[NVOX];

__device__ __forceinline__ unsigned pack2(float a, float b) {
    __half2 h = __floats2half2_rn(a, b);
    return *reinterpret_cast<unsigned*>(&h);
}
__device__ __forceinline__ float2 unpk2(unsigned u) {
    __half2 h = *reinterpret_cast<__half2*>(&u);
    return __half22float2(h);
}

// Opaque pointer copy: blocks ptxas copy-propagation so the four predicated
// loads below cannot be merged back into one divergent LDG.
__device__ __forceinline__ const uint4* launder(const uint4* p) {
    const uint4* q;
    asm volatile("mov.b64 %0, %1;" : "=l"(q) : "l"(p));
    return q;
}

// Warp-partitioned gather: lanes in 8-lane group g execute sub-load g.
// Each sub-LDG touches only that group's distinct lines (~4.5 instead of ~18),
// converting within-LDG replays into cross-LDG wavefronts.
__device__ __forceinline__ uint4 ldg_split4(const uint4* p, unsigned grp) {
    const uint4* p1 = launder(p);
    const uint4* p2 = launder(p);
    const uint4* p3 = launder(p);
    uint4 v;
    asm volatile(
        "{\n\t"
        ".reg .pred q0, q1, q2, q3;\n\t"
        "setp.eq.u32 q0, %8, 0;\n\t"
        "setp.eq.u32 q1, %8, 1;\n\t"
        "setp.eq.u32 q2, %8, 2;\n\t"
        "setp.eq.u32 q3, %8, 3;\n\t"
        "@q0 ld.global.nc.v4.u32 {%0,%1,%2,%3}, [%4];\n\t"
        "@q1 ld.global.nc.v4.u32 {%0,%1,%2,%3}, [%5];\n\t"
        "@q2 ld.global.nc.v4.u32 {%0,%1,%2,%3}, [%6];\n\t"
        "@q3 ld.global.nc.v4.u32 {%0,%1,%2,%3}, [%7];\n\t"
        "}"
        : "=r"(v.x), "=r"(v.y), "=r"(v.z), "=r"(v.w)
        : "l"(p), "l"(p1), "l"(p2), "l"(p3), "r"(grp));
    return v;
}

// ---------------------------------------------------------------------------
// Repack: theta (x,y,z,c) f32 -> g_grid[(x*NZ+z)*NY+y] fp16 z-pair entries.
// Per-block slab = (1 x, TY y, full z): contiguous source -> float4 streaming.
// ---------------------------------------------------------------------------
static constexpr int TY = 10;                // y-rows per block
static constexpr int ROWF = NZ * 3;          // 480 floats per y-row
static constexpr int SROW = ROWF + 3;        // 483: mod 32 = 3 -> conflict-free

__global__ void __launch_bounds__(256)
repack_kernel(const float* __restrict__ theta) {
    __shared__ float s[TY * SROW];           // 19,320 B

    int b = blockIdx.x;
    int tyi = b % (NY / TY);                 // 16 y-tiles
    int x   = b / (NY / TY);
    int y0 = tyi * TY;

    const float4* src = reinterpret_cast<const float4*>(
        theta + (size_t)(x * NY + y0) * ROWF);
    for (int t = threadIdx.x; t < TY * ROWF / 4; t += 256) {
        float4 v = __ldcs(src + t);
        int off = t * 4;                     // never crosses a 480-float row
        int row = off / ROWF;
        int col = off - row * ROWF;
        float* d = s + row * SROW + col;
        d[0] = v.x; d[1] = v.y; d[2] = v.z; d[3] = v.w;
    }
    __syncthreads();

    for (int e = threadIdx.x; e < NZ * TY; e += 256) {
        int y = e % TY;
        int z = e / TY;
        const float* r = s + y * SROW + z * 3;
        float a0 = r[0], a1 = r[1], a2 = r[2];
        bool in = (z + 1 < NZ);              // z-edge partner weight is 0
        float b0 = in ? r[3] : 0.0f;
        float b1 = in ? r[4] : 0.0f;
        float b2 = in ? r[5] : 0.0f;
        uint4 E;
        E.x = pack2(a0, a1);
        E.y = pack2(a2, 0.0f);
        E.z = pack2(b0, b1);
        E.w = pack2(b2, 0.0f);
        g_grid[(x * NZ + z) * NY + (y0 + y)] = E;
    }
}

// ---------------------------------------------------------------------------
// Trilerp: 2 threads per point (lane 2j -> y-row iy, lane 2j+1 -> iy+1; their
// addresses in each gather are 16B apart -> merged wavefront). Gathers issued
// as 4-way warp-partitioned sub-LDGs (see ldg_split4).
// ---------------------------------------------------------------------------
__global__ void __launch_bounds__(256)
trilerp_kernel(const float* __restrict__ coords,
               float* __restrict__ out,
               int n) {
    int gid = blockIdx.x * blockDim.x + threadIdx.x;
    int p = gid >> 1;        // point index
    int r = gid & 1;         // y-role within the lane pair
    if (p >= n) return;
    unsigned grp = (threadIdx.x >> 3) & 3;   // 8-lane group within warp

    float cx = __ldcs(coords + 3 * p + 0);
    float cy = __ldcs(coords + 3 * p + 1);
    float cz = __ldcs(coords + 3 * p + 2);

    float px = cx * (float)(NX - 1);
    float py = cy * (float)(NY - 1);
    float pz = cz * (float)(NZ - 1);
    float fx = floorf(px), fy = floorf(py), fz = floorf(pz);
    float tx = px - fx, ty = py - fy, tz = pz - fz;
    int ix = (int)fx, iy = (int)fy, iz = (int)fz;

    // Per-axis validity folded into axis weights (reference: cval=0 outside).
    bool vx0 = (ix >= 0) && (ix < NX);
    bool vx1 = (ix + 1 >= 0) && (ix + 1 < NX);
    bool vy0 = (iy >= 0) && (iy < NY);
    bool vy1 = (iy + 1 >= 0) && (iy + 1 < NY);
    bool vz0 = (iz >= 0) && (iz < NZ);
    bool vz1 = (iz + 1 >= 0) && (iz + 1 < NZ);

    float wx0 = vx0 ? (1.0f - tx) : 0.0f;
    float wx1 = vx1 ? tx : 0.0f;
    float wy0 = vy0 ? (1.0f - ty) : 0.0f;
    float wy1 = vy1 ? ty : 0.0f;
    float wz0 = vz0 ? (1.0f - tz) : 0.0f;
    float wz1 = vz1 ? tz : 0.0f;

    int ix0 = min(max(ix, 0), NX - 1);
    int ix1 = min(max(ix + 1, 0), NX - 1);
    int iy0 = min(max(iy, 0), NY - 1);
    int iz0 = min(max(iz, 0), NZ - 1);

    int yr = min(iy0 + r, NY - 1);       // this lane's y row
    float wyr = r ? wy1 : wy0;

    int e0 = (ix0 * NZ + iz0) * NY + yr;
    int e1 = (ix1 * NZ + iz0) * NY + yr;

    // Warp-partitioned gathers (4 sub-LDGs each, ~4.5 lines per sub-LDG).
    uint4 A = ldg_split4(&g_grid[e0], grp);  // x0 entry: z-pair at (x0, yr)
    uint4 B = ldg_split4(&g_grid[e1], grp);  // x1 entry: z-pair at (x1, yr)

    float2 Az0 = unpk2(A.x);  float Az0z = unpk2(A.y).x;
    float2 Az1 = unpk2(A.z);  float Az1z = unpk2(A.w).x;
    float2 Bz0 = unpk2(B.x);  float Bz0z = unpk2(B.y).x;
    float2 Bz1 = unpk2(B.z);  float Bz1z = unpk2(B.w).x;

    // z-interp, then x-interp, scaled by this lane's y weight.
    float sx = wyr * (wx0 * fmaf(wz0, Az0.x, wz1 * Az1.x) +
                      wx1 * fmaf(wz0, Bz0.x, wz1 * Bz1.x));
    float sy = wyr * (wx0 * fmaf(wz0, Az0.y, wz1 * Az1.y) +
                      wx1 * fmaf(wz0, Bz0.y, wz1 * Bz1.y));
    float sz = wyr * (wx0 * fmaf(wz0, Az0z, wz1 * Az1z) +
                      wx1 * fmaf(wz0, Bz0z, wz1 * Bz1z));

    // Combine the two y rows across the lane pair.
    unsigned mask = __activemask();
    sx += __shfl_xor_sync(mask, sx, 1);
    sy += __shfl_xor_sync(mask, sy, 1);
    sz += __shfl_xor_sync(mask, sz, 1);

    if (r == 0) {
        __stcs(out + 3 * p + 0, sx);
        __stcs(out + 3 * p + 1, sy);
        __stcs(out + 3 * p + 2, sz);
    }
}

extern "C" void kernel_launch(void* const* d_in, const int* in_sizes, int n_in,
                              void* d_out, int out_size) {
    const float* coords = (const float*)d_in[0];   // (N_POINTS, 3) f32
    const float* theta  = (const float*)d_in[1];   // (160,160,160,3) f32
    float* out = (float*)d_out;                    // (N_POINTS, 3) f32

    int n = in_sizes[0] / 3;

    int repack_blocks = NX * (NY / TY);            // 160 * 16 = 2560
    repack_kernel<<<repack_blocks, 256>>>(theta);

    long long threads = 2LL * n;
    int blocks = (int)((threads + 255) / 256);
    trilerp_kernel<<<blocks, 256>>>(coords, out, n);
}

// round 15
// speedup vs baseline: 1.3347x; 1.3347x over previous
#include <cuda_runtime.h>
#include <cuda_fp16.h>

// DeformationGrid: trilinear interpolation of a (160,160,160,3) f32 grid at
// 4,194,304 random points.
//
// R14 (= R12 minus the illegal L2::evict_last 128-bit form): lane-pair
// trilerp with the merge axis swapped y<->z so the packed grid keeps the
// NATURAL z-fastest order:
//   E[(x*NY+y)*NZ+z] = { v(x,y,z).xyz f16, v(x,y+1,z).xyz f16 }   (16B)
// Lane pair splits z (lane r -> z=iz+r; addresses 16B apart -> merged L1
// wavefront; 2.25 wf/pt unchanged by symmetry). The repack is a pure
// sequential stream (entry index == voxel index, partner = +480 floats):
// no transpose -> DRAM-bound.

static constexpr int NX = 160, NY = 160, NZ = 160;
static constexpr int NVOX = NX * NY * NZ;          // 4,096,000

// 16B fp16 y-pair entry, natural z-fastest order. 65.5 MB (L2-resident).
__device__ uint4 g_grid[NVOX];

__device__ __forceinline__ unsigned pack2(float a, float b) {
    __half2 h = __floats2half2_rn(a, b);
    return *reinterpret_cast<unsigned*>(&h);
}
__device__ __forceinline__ float2 unpk2(unsigned u) {
    __half2 h = *reinterpret_cast<__half2*>(&u);
    return __half22float2(h);
}

// ---------------------------------------------------------------------------
// Repack: pure sequential stream. Block = 256 consecutive entries. Source
// span = floats [3*v0, 3*v0 + 768 + 480): entry v needs theta[3v..3v+2] (own
// voxel) and theta[3v+480..3v+482] (y+1 partner, same x, same z). Stage the
// span in SMEM via float4 streaming loads; 3-stride SMEM reads are
// conflict-free (gcd(3,32)=1).
// ---------------------------------------------------------------------------
static constexpr int RB = 256;                 // entries per block
static constexpr int SPAN4 = (3 * RB + 480 + 3) / 4;   // 312 float4

__global__ void __launch_bounds__(RB)
repack_kernel(const float* __restrict__ theta) {
    __shared__ float4 s4[SPAN4];               // 4992 B
    const float* s = reinterpret_cast<const float*>(s4);

    int v0 = blockIdx.x * RB;
    long long g0 = (long long)3 * v0 / 4;      // 3*v0 divisible by 4 (v0 mult of 256)
    const float4* src = reinterpret_cast<const float4*>(theta);
    const long long lim4 = (long long)3 * NVOX / 4;

    for (int t = threadIdx.x; t < SPAN4; t += RB) {
        long long gi = g0 + t;
        float4 v = (gi < lim4) ? __ldcs(src + gi)
                               : make_float4(0.f, 0.f, 0.f, 0.f);
        s4[t] = v;
    }
    __syncthreads();

    int t = threadIdx.x;
    int v = v0 + t;
    int y = (v / NZ) % NY;

    float a0 = s[3 * t + 0];
    float a1 = s[3 * t + 1];
    float a2 = s[3 * t + 2];
    bool in = (y + 1 < NY);                    // y-edge partner weight is 0
    float b0 = in ? s[3 * t + 480] : 0.0f;
    float b1 = in ? s[3 * t + 481] : 0.0f;
    float b2 = in ? s[3 * t + 482] : 0.0f;

    uint4 E;
    E.x = pack2(a0, a1);
    E.y = pack2(a2, 0.0f);
    E.z = pack2(b0, b1);
    E.w = pack2(b2, 0.0f);
    g_grid[v] = E;
}

// ---------------------------------------------------------------------------
// Trilerp: 2 threads per point. Lane 2j handles z=iz, lane 2j+1 handles
// z=iz+1 (entries 16B apart -> merged wavefront). Each entry provides BOTH
// y corners; x0/x1 entries are the two gathers per lane.
// ---------------------------------------------------------------------------
__global__ void __launch_bounds__(256)
trilerp_kernel(const float* __restrict__ coords,
               float* __restrict__ out,
               int n) {
    int gid = blockIdx.x * blockDim.x + threadIdx.x;
    int p = gid >> 1;        // point index
    int r = gid & 1;         // z-role within the lane pair
    if (p >= n) return;

    // Streaming coalesced reads (evict-first: keep L2 for the grid).
    float cx = __ldcs(coords + 3 * p + 0);
    float cy = __ldcs(coords + 3 * p + 1);
    float cz = __ldcs(coords + 3 * p + 2);

    float px = cx * (float)(NX - 1);
    float py = cy * (float)(NY - 1);
    float pz = cz * (float)(NZ - 1);
    float fx = floorf(px), fy = floorf(py), fz = floorf(pz);
    float tx = px - fx, ty = py - fy, tz = pz - fz;
    int ix = (int)fx, iy = (int)fy, iz = (int)fz;

    // Per-axis validity folded into axis weights (reference: cval=0 outside).
    bool vx0 = (ix >= 0) && (ix < NX);
    bool vx1 = (ix + 1 >= 0) && (ix + 1 < NX);
    bool vy0 = (iy >= 0) && (iy < NY);
    bool vy1 = (iy + 1 >= 0) && (iy + 1 < NY);
    bool vz0 = (iz >= 0) && (iz < NZ);
    bool vz1 = (iz + 1 >= 0) && (iz + 1 < NZ);

    float wx0 = vx0 ? (1.0f - tx) : 0.0f;
    float wx1 = vx1 ? tx : 0.0f;
    float wy0 = vy0 ? (1.0f - ty) : 0.0f;
    float wy1 = vy1 ? ty : 0.0f;
    float wz0 = vz0 ? (1.0f - tz) : 0.0f;
    float wz1 = vz1 ? tz : 0.0f;

    int ix0 = min(max(ix, 0), NX - 1);
    int ix1 = min(max(ix + 1, 0), NX - 1);
    int iy0 = min(max(iy, 0), NY - 1);
    int iz0 = min(max(iz, 0), NZ - 1);

    int zr = min(iz0 + r, NZ - 1);       // this lane's z slice
    float wzr = r ? wz1 : wz0;

    int e0 = (ix0 * NY + iy0) * NZ + zr;
    int e1 = (ix1 * NY + iy0) * NZ + zr;

    // Lane-pair addresses are 16B apart within each instruction -> merged wf.
    uint4 A = __ldg(&g_grid[e0]);        // x0 entry: y-pair at (x0, iy0, zr)
    uint4 B = __ldg(&g_grid[e1]);        // x1 entry: y-pair at (x1, iy0, zr)

    float2 Ay0 = unpk2(A.x);  float Ay0z = unpk2(A.y).x;   // v(y)
    float2 Ay1 = unpk2(A.z);  float Ay1z = unpk2(A.w).x;   // v(y+1)
    float2 By0 = unpk2(B.x);  float By0z = unpk2(B.y).x;
    float2 By1 = unpk2(B.z);  float By1z = unpk2(B.w).x;

    // y-interp, then x-interp, scaled by this lane's z weight.
    float sx = wzr * (wx0 * fmaf(wy0, Ay0.x, wy1 * Ay1.x) +
                      wx1 * fmaf(wy0, By0.x, wy1 * By1.x));
    float sy = wzr * (wx0 * fmaf(wy0, Ay0.y, wy1 * Ay1.y) +
                      wx1 * fmaf(wy0, By0.y, wy1 * By1.y));
    float sz = wzr * (wx0 * fmaf(wy0, Ay0z, wy1 * Ay1z) +
                      wx1 * fmaf(wy0, By0z, wy1 * By1z));

    // Combine the two z slices across the lane pair.
    unsigned mask = __activemask();
    sx += __shfl_xor_sync(mask, sx, 1);
    sy += __shfl_xor_sync(mask, sy, 1);
    sz += __shfl_xor_sync(mask, sz, 1);

    if (r == 0) {
        __stcs(out + 3 * p + 0, sx);
        __stcs(out + 3 * p + 1, sy);
        __stcs(out + 3 * p + 2, sz);
    }
}

extern "C" void kernel_launch(void* const* d_in, const int* in_sizes, int n_in,
                              void* d_out, int out_size) {
    const float* coords = (const float*)d_in[0];   // (N_POINTS, 3) f32
    const float* theta  = (const float*)d_in[1];   // (160,160,160,3) f32
    float* out = (float*)d_out;                    // (N_POINTS, 3) f32

    int n = in_sizes[0] / 3;

    repack_kernel<<<NVOX / RB, RB>>>(theta);       // 16000 blocks

    long long threads = 2LL * n;
    int blocks = (int)((threads + 255) / 256);
    trilerp_kernel<<<blocks, 256>>>(coords, out, n);
}